// round 12
// baseline (speedup 1.0000x reference)
#include <cuda_runtime.h>
#include <cuda_fp16.h>
#include <mma.h>
#include <math.h>
#include <cstdint>

using namespace nvcuda;

#define NTOK 4096
#define DDIM 1024
#define HDIM 4096
#define ODIM 1024
#define NEXP 8
#define NPAIR 8192

#define BM 128
#define BN 256
#define BK 128
#define ALD 136     // A smem row stride (halfs) -> 272B
#define BLD 264     // B smem row stride (halfs) -> 528B
#define CLD 264     // C smem row stride (floats)

#define A_STAGE 34816             // 128*136*2
#define B_STAGE 67584             // 128*264*2
#define STG (A_STAGE + B_STAGE)   // 102400
#define OFF_B A_STAGE
#define NSTAGE 2
#define SMEM_GEMM (NSTAGE * STG)  // 204800 (C tile 128*264*4=135168 aliases)
#define RLD 1028                  // router smem row stride (floats)
#define SMEM_ROUTER (16 * RLD * 4)

__device__ __forceinline__ uint32_t smem_u32(const void* p) {
    uint32_t a;
    asm("{ .reg .u64 t; cvta.to.shared.u64 t, %1; cvt.u32.u64 %0, t; }" : "=r"(a) : "l"(p));
    return a;
}
#define CP_ASYNC16(dst, src, sz) \
    asm volatile("cp.async.cg.shared.global [%0], [%1], 16, %2;" \
                 :: "r"(dst), "l"(src), "r"(sz))
#define CP_COMMIT() asm volatile("cp.async.commit_group;")
#define CP_WAIT0()  asm volatile("cp.async.wait_group 0;")

// ---------------- scratch (device globals) ----------------
__device__ int   g_cnt[NEXP];
__device__ int   g_tok[NEXP * NTOK];
__device__ float g_gate[NEXP * NTOK];
__device__ __half g_xh[NTOK * DDIM];                 // fp16(x)
__device__ __half g_w1h[NEXP * DDIM * HDIM];         // fp16(W1)
__device__ __half g_w2h[NEXP * HDIM * ODIM];         // fp16(W2)
__device__ __half g_h[(size_t)NPAIR * HDIM];         // fp16(h)

// ---------------- x: fp32 -> fp16 ----------------
__global__ void conv_x_kernel(const float4* __restrict__ src) {
    int i = blockIdx.x * blockDim.x + threadIdx.x;
    if (i >= NTOK * DDIM / 4) return;
    float4 v = src[i];
    __half2* dst = (__half2*)g_xh;
    dst[2 * i]     = __halves2half2(__float2half_rn(v.x), __float2half_rn(v.y));
    dst[2 * i + 1] = __halves2half2(__float2half_rn(v.z), __float2half_rn(v.w));
}

// ---------------- W1 + W2: fp32 -> fp16 ----------------
__global__ void conv_w_kernel(const float4* __restrict__ W1,
                              const float4* __restrict__ W2) {
    const int n4 = NEXP * DDIM * HDIM / 4;
    int i = blockIdx.x * blockDim.x + threadIdx.x;
    if (i >= 2 * n4) return;
    bool second = i >= n4;
    int j = second ? i - n4 : i;
    float4 v = second ? W2[j] : W1[j];
    __half2* hi = (__half2*)(second ? g_w2h : g_w1h);
    hi[2 * j]     = __halves2half2(__float2half_rn(v.x), __float2half_rn(v.y));
    hi[2 * j + 1] = __halves2half2(__float2half_rn(v.z), __float2half_rn(v.w));
}

// ---------------- router: expert-per-lane, 2 tokens/warp ----------------
__global__ void router_kernel(const float* __restrict__ x,
                              const float* __restrict__ noise,
                              const float* __restrict__ Wg,
                              const float* __restrict__ bg,
                              const float* __restrict__ Wn,
                              const float* __restrict__ bn) {
    extern __shared__ float Ws[];  // [16][RLD] rows: 0..7 Wg cols, 8..15 Wn cols
    int tid = threadIdx.x;
    for (int idx = tid; idx < DDIM * NEXP; idx += blockDim.x) {
        int k = idx >> 3, o = idx & 7;
        Ws[o * RLD + k]       = Wg[idx];
        Ws[(8 + o) * RLD + k] = Wn[idx];
    }
    __syncthreads();
    int warp = tid >> 5, lane = tid & 31;
    int o = lane & 15, half = lane >> 4;
    int t = blockIdx.x * 16 + warp * 2 + half;

    const float4* xr = (const float4*)(x + (size_t)t * DDIM);
    const float4* wr = (const float4*)(Ws + o * RLD);
    float acc = 0.f;
#pragma unroll 8
    for (int k = 0; k < 256; ++k) {
        float4 xv = xr[k];
        float4 wv = wr[k];
        acc += xv.x * wv.x + xv.y * wv.y + xv.z * wv.z + xv.w * wv.w;
    }
    float nl_other = __shfl_sync(0xffffffffu, acc, (lane + 8) & 31);
    float noisy = -3.4e38f;
    if (o < 8) {
        float lg = acc + bg[o];
        float nl = nl_other + bn[o];
        float sp = nl > 20.f ? nl : log1pf(expf(nl));
        noisy = lg + noise[(size_t)t * 8 + o] * sp;
    }
    float v[8];
#pragma unroll
    for (int oo = 0; oo < 8; ++oo)
        v[oo] = __shfl_sync(0xffffffffu, noisy, (half << 4) + oo);
    if (o == 0) {
        int i1 = 0; float v1 = v[0];
#pragma unroll
        for (int oo = 1; oo < 8; ++oo) if (v[oo] > v1) { v1 = v[oo]; i1 = oo; }
        int i2 = 0; float v2 = -3.4e38f;
#pragma unroll
        for (int oo = 0; oo < 8; ++oo) if (oo != i1 && v[oo] > v2) { v2 = v[oo]; i2 = oo; }
        float ex = expf(v2 - v1);
        float inv = 1.f / (1.f + ex);
        int p1 = atomicAdd(&g_cnt[i1], 1);
        g_tok[i1 * NTOK + p1]  = t;
        g_gate[i1 * NTOK + p1] = inv;
        int p2 = atomicAdd(&g_cnt[i2], 1);
        g_tok[i2 * NTOK + p2]  = t;
        g_gate[i2 * NTOK + p2] = ex * inv;
    }
}

// ---------------- grouped GEMM (fp16 wmma 64x64/warp, BK=128, 2-stage) ----------------
// SECOND=false: h = relu(gather(xh) @ W1h[e] + b1[e]) -> g_h (fp16)
// SECOND=true : out += gate * (h @ W2h[e] + b2[e]); split-K over blockIdx.z
template <bool SECOND>
__global__ void __launch_bounds__(256, 1)
moe_gemm_kernel(const float* __restrict__ bias, float* __restrict__ out) {
    constexpr int NDIM = SECOND ? ODIM : HDIM;
    constexpr int KSLICE = SECOND ? (HDIM / 2) : DDIM;   // 2048 / 1024
    constexpr int KT = KSLICE / BK;                       // 16 / 8

    int e  = blockIdx.y >> 5;
    int mt = blockIdx.y & 31;
    int cnt = g_cnt[e];
    int m0 = mt * BM;
    if (m0 >= cnt) return;
    int off = 0;
#pragma unroll
    for (int q = 0; q < NEXP; ++q) off += (q < e) ? g_cnt[q] : 0;
    int n0 = blockIdx.x * BN;
    int kbase = SECOND ? (int)(blockIdx.z * KSLICE) : 0;
    int tid = threadIdx.x;
    int w = tid >> 5;
    int wm = (w & 1) * 64, wn = (w >> 1) * 64;

    extern __shared__ __align__(128) char raw[];
    uint32_t sbase = smem_u32(raw);

    const __half* Asrc = SECOND ? g_h : g_xh;
    const __half* Bsrc = SECOND ? g_w2h : g_w1h;
    constexpr int KFULL = SECOND ? HDIM : DDIM;

    // A: 2 threads per row, each 64 halfs (8 x 16B chunks)
    int arow = tid >> 1;
    int acb  = (tid & 1) * 64;    // col base (halfs)
    int apos = m0 + arow;
    bool aval = apos < cnt;
    uint32_t asz = aval ? 16u : 0u;
    size_t abase;
    if (SECOND) {
        abase = (size_t)(off + (aval ? apos : 0)) * HDIM + kbase + acb;
    } else {
        int token = aval ? g_tok[e * NTOK + apos] : 0;
        abase = (size_t)token * DDIM + acb;
    }
    uint32_t adst = sbase + arow * (ALD * 2) + acb * 2;
    // B: chunk id = tid + 256*i (i<16): row = id>>5, c16 = id&31
    size_t bbase0 = (size_t)e * KFULL * NDIM + (size_t)(kbase + (tid >> 5)) * NDIM + n0 + (tid & 31) * 8;
    uint32_t bdst0 = sbase + OFF_B + (tid >> 5) * (BLD * 2) + (tid & 31) * 16;

    auto fill = [&](int s, int kt) {
        int ko = kt * BK;
        uint32_t sb = s * STG;
        const char* ap = (const char*)(Asrc + abase + ko);
        uint32_t ad = adst + sb;
#pragma unroll
        for (int c = 0; c < 8; ++c)
            CP_ASYNC16(ad + c * 16, ap + c * 16, asz);
        const char* bp = (const char*)(Bsrc + bbase0 + (size_t)ko * NDIM);
        uint32_t bd = bdst0 + sb;
#pragma unroll
        for (int i = 0; i < 16; ++i)
            CP_ASYNC16(bd + i * 8 * (BLD * 2), bp + (size_t)i * 8 * NDIM * 2, 16u);
        CP_COMMIT();
    };

    wmma::fragment<wmma::accumulator, 16, 16, 16, float> acc[4][4];
#pragma unroll
    for (int i = 0; i < 4; ++i)
#pragma unroll
        for (int j = 0; j < 4; ++j) wmma::fill_fragment(acc[i][j], 0.f);

    auto compute = [&](int s) {
        const __half* Ah = (const __half*)(raw + s * STG);
        const __half* Bh = (const __half*)(raw + s * STG + OFF_B);
#pragma unroll
        for (int kk = 0; kk < BK; kk += 16) {
            wmma::fragment<wmma::matrix_a, 16, 16, 16, __half, wmma::row_major> fa[4];
            wmma::fragment<wmma::matrix_b, 16, 16, 16, __half, wmma::row_major> fb[4];
#pragma unroll
            for (int i = 0; i < 4; ++i)
                wmma::load_matrix_sync(fa[i], Ah + (wm + 16 * i) * ALD + kk, ALD);
#pragma unroll
            for (int j = 0; j < 4; ++j)
                wmma::load_matrix_sync(fb[j], Bh + kk * BLD + wn + 16 * j, BLD);
#pragma unroll
            for (int i = 0; i < 4; ++i)
#pragma unroll
                for (int j = 0; j < 4; ++j)
                    wmma::mma_sync(acc[i][j], fa[i], fb[j], acc[i][j]);
        }
    };

    fill(0, 0);
    CP_WAIT0();
    __syncthreads();
#pragma unroll 1
    for (int kt = 0; kt < KT; ++kt) {
        if (kt + 1 < KT) fill((kt + 1) & 1, kt + 1);
        compute(kt & 1);
        if (kt + 1 < KT) {
            CP_WAIT0();
            __syncthreads();
        }
    }

    // epilogue via smem C tile (aliased over stage buffers)
    __syncthreads();
    float* sC = (float*)raw;
#pragma unroll
    for (int i = 0; i < 4; ++i)
#pragma unroll
        for (int j = 0; j < 4; ++j)
            wmma::store_matrix_sync(sC + (wm + 16 * i) * CLD + wn + 16 * j, acc[i][j], CLD,
                                    wmma::mem_row_major);
    __syncthreads();

    if (!SECOND) {
        for (int q = tid; q < BM * (BN / 8); q += 256) {
            int r = q >> 5;
            int c = (q & 31) * 8;
            int pos = m0 + r;
            if (pos >= cnt) continue;
            int nb = n0 + c;
            uint4 pk;
            __half2 p[4];
#pragma unroll
            for (int u = 0; u < 4; ++u) {
                float v0 = sC[r * CLD + c + 2 * u]     + bias[e * NDIM + nb + 2 * u];
                float v1 = sC[r * CLD + c + 2 * u + 1] + bias[e * NDIM + nb + 2 * u + 1];
                p[u] = __halves2half2(__float2half_rn(fmaxf(v0, 0.f)),
                                      __float2half_rn(fmaxf(v1, 0.f)));
            }
            pk.x = *(uint32_t*)&p[0]; pk.y = *(uint32_t*)&p[1];
            pk.z = *(uint32_t*)&p[2]; pk.w = *(uint32_t*)&p[3];
            *(uint4*)(g_h + (size_t)(off + pos) * HDIM + nb) = pk;
        }
    } else {
        bool add_bias = (blockIdx.z == 0);
        for (int q = tid; q < BM * (BN / 4); q += 256) {
            int r = q >> 6;
            int c = (q & 63) * 4;
            int pos = m0 + r;
            if (pos >= cnt) continue;
            float gate = g_gate[e * NTOK + pos];
            int token  = g_tok[e * NTOK + pos];
            int nb = n0 + c;
            float* op = out + (size_t)token * ODIM + nb;
#pragma unroll
            for (int u = 0; u < 4; ++u) {
                float v = sC[r * CLD + c + u];
                if (add_bias) v += bias[e * NDIM + nb + u];
                atomicAdd(op + u, v * gate);
            }
        }
    }
}

// ---------------- launch ----------------
extern "C" void kernel_launch(void* const* d_in, const int* in_sizes, int n_in,
                              void* d_out, int out_size) {
    const float* x     = (const float*)d_in[0];
    const float* noise = (const float*)d_in[1];
    const float* Wg    = (const float*)d_in[2];
    const float* bg    = (const float*)d_in[3];
    const float* Wn    = (const float*)d_in[4];
    const float* bn    = (const float*)d_in[5];
    const float* W1    = (const float*)d_in[6];
    const float* b1    = (const float*)d_in[7];
    const float* W2    = (const float*)d_in[8];
    const float* b2    = (const float*)d_in[9];
    (void)in_sizes; (void)n_in;

    void* cnt_ptr;
    cudaGetSymbolAddress(&cnt_ptr, g_cnt);

    cudaFuncSetAttribute(router_kernel, cudaFuncAttributeMaxDynamicSharedMemorySize, SMEM_ROUTER);
    cudaFuncSetAttribute(moe_gemm_kernel<false>, cudaFuncAttributeMaxDynamicSharedMemorySize, SMEM_GEMM);
    cudaFuncSetAttribute(moe_gemm_kernel<true>,  cudaFuncAttributeMaxDynamicSharedMemorySize, SMEM_GEMM);

    // launch order: gemm1 is profiled launch index 5 (ncu -s 5 -c 1)
    cudaMemsetAsync(cnt_ptr, 0, NEXP * sizeof(int));                       // 0
    cudaMemsetAsync(d_out, 0, (size_t)out_size * sizeof(float));           // 1

    int n4x = NTOK * DDIM / 4;
    conv_x_kernel<<<(n4x + 255) / 256, 256>>>((const float4*)x);           // 2
    int n4w = NEXP * DDIM * HDIM / 4;
    conv_w_kernel<<<(2 * n4w + 255) / 256, 256>>>((const float4*)W1,
                                                  (const float4*)W2);      // 3
    router_kernel<<<NTOK / 16, 256, SMEM_ROUTER>>>(x, noise, Wg, bg, Wn, bn); // 4

    moe_gemm_kernel<false><<<dim3(HDIM / BN, NEXP * 32, 1), 256, SMEM_GEMM>>>(b1, nullptr);      // 5
    moe_gemm_kernel<true> <<<dim3(ODIM / BN, NEXP * 32, 2), 256, SMEM_GEMM>>>(b2, (float*)d_out); // 6
}

// round 13
// speedup vs baseline: 1.0016x; 1.0016x over previous
#include <cuda_runtime.h>
#include <cuda_fp16.h>
#include <mma.h>
#include <math.h>
#include <cstdint>

using namespace nvcuda;

#define NTOK 4096
#define DDIM 1024
#define HDIM 4096
#define ODIM 1024
#define NEXP 8
#define NPAIR 8192
#define MAXMT 80

#define BM 128
#define BN 256
#define BK 64
#define ALD 72      // A smem row stride (halfs)
#define BLD 264     // B smem row stride (halfs)
#define CLD 264     // C smem row stride (floats)

#define A_STAGE 18432             // 128*72*2
#define B_STAGE 33792             // 64*264*2
#define STG (A_STAGE + B_STAGE)   // 52224
#define OFF_B A_STAGE
#define NSTAGE 3
#define SMEM_GEMM (NSTAGE * STG)  // 156672 (C tile 128*264*4=135168 aliases)
#define RLD 1028                  // router smem row stride (floats)
#define SMEM_ROUTER (16 * RLD * 4)

__device__ __forceinline__ uint32_t smem_u32(const void* p) {
    uint32_t a;
    asm("{ .reg .u64 t; cvta.to.shared.u64 t, %1; cvt.u32.u64 %0, t; }" : "=r"(a) : "l"(p));
    return a;
}
#define CP_ASYNC16(dst, src, sz) \
    asm volatile("cp.async.cg.shared.global [%0], [%1], 16, %2;" \
                 :: "r"(dst), "l"(src), "r"(sz))
#define CP_COMMIT() asm volatile("cp.async.commit_group;")
#define CP_WAIT0()  asm volatile("cp.async.wait_group 0;")
#define CP_WAIT1()  asm volatile("cp.async.wait_group 1;")

// ---------------- scratch (device globals) ----------------
__device__ int   g_cnt[NEXP];
__device__ int   g_tok[NEXP * NTOK];
__device__ float g_gate[NEXP * NTOK];
__device__ __half g_xh[NTOK * DDIM];                 // fp16(x)
__device__ __half g_w1h[NEXP * DDIM * HDIM];         // fp16(W1)
__device__ __half g_w2h[NEXP * HDIM * ODIM];         // fp16(W2)
__device__ __half g_h[(size_t)NPAIR * HDIM];         // fp16(h)
__device__ int g_mte[MAXMT], g_mtm[MAXMT], g_mto[MAXMT], g_mtc[MAXMT];
__device__ int g_done[MAXMT];
__device__ int g_njobs1, g_njobs, g_job;

// ---------------- W1 + W2: fp32 -> fp16 ----------------
__global__ void conv_w_kernel(const float4* __restrict__ W1,
                              const float4* __restrict__ W2) {
    const int n4 = NEXP * DDIM * HDIM / 4;
    int i = blockIdx.x * blockDim.x + threadIdx.x;
    if (i >= 2 * n4) return;
    bool second = i >= n4;
    int j = second ? i - n4 : i;
    float4 v = second ? W2[j] : W1[j];
    __half2* hi = (__half2*)(second ? g_w2h : g_w1h);
    hi[2 * j]     = __halves2half2(__float2half_rn(v.x), __float2half_rn(v.y));
    hi[2 * j + 1] = __halves2half2(__float2half_rn(v.z), __float2half_rn(v.w));
}

// ---------------- router: expert-per-lane, 2 tokens/warp; also emits fp16(x) ----------------
__global__ void router_kernel(const float* __restrict__ x,
                              const float* __restrict__ noise,
                              const float* __restrict__ Wg,
                              const float* __restrict__ bg,
                              const float* __restrict__ Wn,
                              const float* __restrict__ bn) {
    extern __shared__ float Ws[];  // [16][RLD] rows: 0..7 Wg cols, 8..15 Wn cols
    int tid = threadIdx.x;
    for (int idx = tid; idx < DDIM * NEXP; idx += blockDim.x) {
        int k = idx >> 3, o = idx & 7;
        Ws[o * RLD + k]       = Wg[idx];
        Ws[(8 + o) * RLD + k] = Wn[idx];
    }
    __syncthreads();
    int warp = tid >> 5, lane = tid & 31;
    int o = lane & 15, half = lane >> 4;
    int t = blockIdx.x * 16 + warp * 2 + half;

    const float4* xr = (const float4*)(x + (size_t)t * DDIM);
    const float4* wr = (const float4*)(Ws + o * RLD);
    float acc = 0.f;
#pragma unroll 8
    for (int k = 0; k < 256; ++k) {
        float4 xv = xr[k];
        float4 wv = wr[k];
        acc += xv.x * wv.x + xv.y * wv.y + xv.z * wv.z + xv.w * wv.w;
    }
    float nl_other = __shfl_sync(0xffffffffu, acc, (lane + 8) & 31);
    float noisy = -3.4e38f;
    if (o < 8) {
        float lg = acc + bg[o];
        float nl = nl_other + bn[o];
        float sp = nl > 20.f ? nl : log1pf(expf(nl));
        noisy = lg + noise[(size_t)t * 8 + o] * sp;
    }
    float v[8];
#pragma unroll
    for (int oo = 0; oo < 8; ++oo)
        v[oo] = __shfl_sync(0xffffffffu, noisy, (half << 4) + oo);
    if (o == 0) {
        int i1 = 0; float v1 = v[0];
#pragma unroll
        for (int oo = 1; oo < 8; ++oo) if (v[oo] > v1) { v1 = v[oo]; i1 = oo; }
        int i2 = 0; float v2 = -3.4e38f;
#pragma unroll
        for (int oo = 0; oo < 8; ++oo) if (oo != i1 && v[oo] > v2) { v2 = v[oo]; i2 = oo; }
        float ex = expf(v2 - v1);
        float inv = 1.f / (1.f + ex);
        int p1 = atomicAdd(&g_cnt[i1], 1);
        g_tok[i1 * NTOK + p1]  = t;
        g_gate[i1 * NTOK + p1] = inv;
        int p2 = atomicAdd(&g_cnt[i2], 1);
        g_tok[i2 * NTOK + p2]  = t;
        g_gate[i2 * NTOK + p2] = ex * inv;
    }
    // fused fp32->fp16 conversion of this block's 16 token rows (L1/L2 hot)
    int t0 = blockIdx.x * 16;
    for (int i = tid; i < 16 * (DDIM / 4); i += blockDim.x) {
        int row = i >> 8, col = i & 255;
        float4 vx = *(const float4*)(x + (size_t)(t0 + row) * DDIM + col * 4);
        __half2* dst = (__half2*)(g_xh + (size_t)(t0 + row) * DDIM + col * 4);
        dst[0] = __halves2half2(__float2half_rn(vx.x), __float2half_rn(vx.y));
        dst[1] = __halves2half2(__float2half_rn(vx.z), __float2half_rn(vx.w));
    }
}

// ---------------- scan: m-tile table + job counters ----------------
__global__ void scan_kernel() {
    if (threadIdx.x == 0) {
        int s = 0, nt = 0;
        for (int e = 0; e < NEXP; ++e) {
            int c = g_cnt[e];
            for (int m0 = 0; m0 < c; m0 += BM) {
                g_mte[nt] = e; g_mtm[nt] = m0; g_mto[nt] = s + m0;
                g_mtc[nt] = c; g_done[nt] = 0; ++nt;
            }
            s += c;
        }
        g_njobs1 = nt * 16;       // gemm1: 16 n-tiles of 256 over HDIM
        g_njobs  = nt * 32;       // + gemm2: 4 n-tiles x 4 k-slices
        g_job = 0;
    }
}

// ---------------- fused persistent grouped GEMM (R8 engine) ----------------
// job j < njobs1 : gemm1 tile: h = relu(gather(xh) @ W1h + b1) -> g_h
// job j >= njobs1: gemm2 tile (split-K x4): out += gate*(h @ W2h [+ b2 on slice 0])
__global__ void __launch_bounds__(256, 1)
fused_gemm_kernel(const float* __restrict__ b1, const float* __restrict__ b2,
                  float* __restrict__ out) {
    extern __shared__ __align__(128) char raw[];
    __shared__ int jsh;
    uint32_t sbase = smem_u32(raw);
    int tid = threadIdx.x;
    int w = tid >> 5;
    int wm = (w & 1) * 64, wn = (w >> 1) * 64;
    int njobs1 = g_njobs1, njobs = g_njobs;

    // per-thread constant smem destinations
    uint32_t adst[4];
#pragma unroll
    for (int i = 0; i < 4; ++i) {
        int id = tid + 256 * i;
        adst[i] = sbase + (id >> 3) * (ALD * 2) + (id & 7) * 16;
    }
    uint32_t bdst0 = sbase + OFF_B + (tid >> 5) * (BLD * 2) + (tid & 31) * 16;

    while (true) {
        if (tid == 0) jsh = atomicAdd(&g_job, 1);
        __syncthreads();
        int j = jsh;
        if (j >= njobs) break;
        bool is2 = j >= njobs1;
        int tile, n0, kbase, ndim;
        const __half* Bsrc;
        const float* bias;
        if (!is2) {
            tile = j >> 4; n0 = (j & 15) << 8; kbase = 0;
            ndim = HDIM; Bsrc = g_w1h; bias = b1;
        } else {
            int j2 = j - njobs1;
            tile = j2 >> 4; int rem = j2 & 15;
            n0 = (rem & 3) << 8; kbase = (rem >> 2) << 10;
            ndim = ODIM; Bsrc = g_w2h; bias = b2;
        }
        int e = g_mte[tile], m0 = g_mtm[tile], cnt = g_mtc[tile], gro = g_mto[tile];

        if (is2) {
            if (tid == 0) {
                while (*(volatile int*)&g_done[tile] < 16) __nanosleep(128);
            }
            __syncthreads();
            __threadfence();
        }

        const __half* Asrc = is2 ? g_h : g_xh;
        size_t asrc[4]; uint32_t asz[4];
#pragma unroll
        for (int i = 0; i < 4; ++i) {
            int id = tid + 256 * i;
            int row = id >> 3, c8 = id & 7;
            int pos = m0 + row;
            bool av = pos < cnt;
            asz[i] = av ? 16u : 0u;
            if (is2) {
                asrc[i] = (size_t)(gro + (av ? row : 0)) * HDIM + kbase + c8 * 8;
            } else {
                int token = av ? g_tok[e * NTOK + pos] : 0;
                asrc[i] = (size_t)token * DDIM + c8 * 8;
            }
        }
        size_t bbase0 = (size_t)e * 4194304 +
                        (size_t)(kbase + (tid >> 5)) * ndim + n0 + (tid & 31) * 8;

        auto fill = [&](int s, int kt) {
            int ko = kt * BK;
            uint32_t sb = s * STG;
#pragma unroll
            for (int i = 0; i < 4; ++i)
                CP_ASYNC16(adst[i] + sb, (const char*)(Asrc + asrc[i] + ko), asz[i]);
            const char* bp = (const char*)(Bsrc + bbase0 + (size_t)ko * ndim);
            uint32_t bd = bdst0 + sb;
#pragma unroll
            for (int i = 0; i < 8; ++i)
                CP_ASYNC16(bd + i * 8 * (BLD * 2), bp + (size_t)i * 8 * ndim * 2, 16u);
            CP_COMMIT();
        };

        wmma::fragment<wmma::accumulator, 16, 16, 16, float> acc[4][4];
#pragma unroll
        for (int i = 0; i < 4; ++i)
#pragma unroll
            for (int jj = 0; jj < 4; ++jj) wmma::fill_fragment(acc[i][jj], 0.f);

        auto compute = [&](int s) {
            const __half* Ah = (const __half*)(raw + s * STG);
            const __half* Bh = (const __half*)(raw + s * STG + OFF_B);
#pragma unroll
            for (int kk = 0; kk < BK; kk += 16) {
                wmma::fragment<wmma::matrix_a, 16, 16, 16, __half, wmma::row_major> fa[4];
                wmma::fragment<wmma::matrix_b, 16, 16, 16, __half, wmma::row_major> fb[4];
#pragma unroll
                for (int i = 0; i < 4; ++i)
                    wmma::load_matrix_sync(fa[i], Ah + (wm + 16 * i) * ALD + kk, ALD);
#pragma unroll
                for (int jj = 0; jj < 4; ++jj)
                    wmma::load_matrix_sync(fb[jj], Bh + kk * BLD + wn + 16 * jj, BLD);
#pragma unroll
                for (int i = 0; i < 4; ++i)
#pragma unroll
                    for (int jj = 0; jj < 4; ++jj)
                        wmma::mma_sync(acc[i][jj], fa[i], fb[jj], acc[i][jj]);
            }
        };

        constexpr int KT = 16;
        fill(0, 0);
        fill(1, 1);
#pragma unroll 1
        for (int kt = 0; kt < KT; ++kt) {
            if (KT - kt >= 2) CP_WAIT1(); else CP_WAIT0();
            __syncthreads();
            if (kt + 2 < KT) fill((kt + 2) % NSTAGE, kt + 2);
            compute(kt % NSTAGE);
        }

        __syncthreads();
        float* sC = (float*)raw;
#pragma unroll
        for (int i = 0; i < 4; ++i)
#pragma unroll
            for (int jj = 0; jj < 4; ++jj)
                wmma::store_matrix_sync(sC + (wm + 16 * i) * CLD + wn + 16 * jj, acc[i][jj],
                                        CLD, wmma::mem_row_major);
        __syncthreads();

        if (!is2) {
            for (int q = tid; q < BM * (BN / 8); q += 256) {
                int r = q >> 5;
                int c = (q & 31) * 8;
                int pos = m0 + r;
                if (pos >= cnt) continue;
                int nb = n0 + c;
                uint4 pk;
                __half2 p[4];
#pragma unroll
                for (int u = 0; u < 4; ++u) {
                    float v0 = sC[r * CLD + c + 2 * u]     + bias[e * ndim + nb + 2 * u];
                    float v1 = sC[r * CLD + c + 2 * u + 1] + bias[e * ndim + nb + 2 * u + 1];
                    p[u] = __halves2half2(__float2half_rn(fmaxf(v0, 0.f)),
                                          __float2half_rn(fmaxf(v1, 0.f)));
                }
                pk.x = *(uint32_t*)&p[0]; pk.y = *(uint32_t*)&p[1];
                pk.z = *(uint32_t*)&p[2]; pk.w = *(uint32_t*)&p[3];
                *(uint4*)(g_h + (size_t)(gro + r) * HDIM + nb) = pk;
            }
            __threadfence();
            __syncthreads();
            if (tid == 0) atomicAdd(&g_done[tile], 1);
        } else {
            bool add_bias = (kbase == 0);
            for (int q = tid; q < BM * (BN / 4); q += 256) {
                int r = q >> 6;
                int c = (q & 63) * 4;
                int pos = m0 + r;
                if (pos >= cnt) continue;
                float gate = g_gate[e * NTOK + pos];
                int token  = g_tok[e * NTOK + pos];
                int nb = n0 + c;
                float* op = out + (size_t)token * ODIM + nb;
#pragma unroll
                for (int u = 0; u < 4; ++u) {
                    float v = sC[r * CLD + c + u];
                    if (add_bias) v += bias[e * ndim + nb + u];
                    atomicAdd(op + u, v * gate);
                }
            }
        }
    }
}

// ---------------- launch ----------------
extern "C" void kernel_launch(void* const* d_in, const int* in_sizes, int n_in,
                              void* d_out, int out_size) {
    const float* x     = (const float*)d_in[0];
    const float* noise = (const float*)d_in[1];
    const float* Wg    = (const float*)d_in[2];
    const float* bg    = (const float*)d_in[3];
    const float* Wn    = (const float*)d_in[4];
    const float* bn    = (const float*)d_in[5];
    const float* W1    = (const float*)d_in[6];
    const float* b1    = (const float*)d_in[7];
    const float* W2    = (const float*)d_in[8];
    const float* b2    = (const float*)d_in[9];
    (void)in_sizes; (void)n_in;

    void* cnt_ptr;
    cudaGetSymbolAddress(&cnt_ptr, g_cnt);

    int dev = 0, nsm = 148;
    cudaGetDevice(&dev);
    cudaDeviceGetAttribute(&nsm, cudaDevAttrMultiProcessorCount, dev);

    cudaFuncSetAttribute(router_kernel, cudaFuncAttributeMaxDynamicSharedMemorySize, SMEM_ROUTER);
    cudaFuncSetAttribute(fused_gemm_kernel, cudaFuncAttributeMaxDynamicSharedMemorySize, SMEM_GEMM);

    // launches: 0 memset cnt, 1 memset out, 2 conv_w, 3 router, 4 scan, 5 fused (profiled)
    cudaMemsetAsync(cnt_ptr, 0, NEXP * sizeof(int));
    cudaMemsetAsync(d_out, 0, (size_t)out_size * sizeof(float));

    int n4w = NEXP * DDIM * HDIM / 4;
    conv_w_kernel<<<(2 * n4w + 255) / 256, 256>>>((const float4*)W1, (const float4*)W2);
    router_kernel<<<NTOK / 16, 256, SMEM_ROUTER>>>(x, noise, Wg, bg, Wn, bn);
    scan_kernel<<<1, 32>>>();

    fused_gemm_kernel<<<nsm, 256, SMEM_GEMM>>>(b1, b2, (float*)d_out);
}

// round 14
// speedup vs baseline: 1.1158x; 1.1141x over previous
#include <cuda_runtime.h>
#include <cuda_fp16.h>
#include <mma.h>
#include <math.h>
#include <cstdint>

using namespace nvcuda;

#define NTOK 4096
#define DDIM 1024
#define HDIM 4096
#define ODIM 1024
#define NEXP 8
#define NPAIR 8192

#define BM 128
#define BN 256
#define BK 64
#define ALD 72      // A smem row stride (halfs)
#define BLD 264     // B smem row stride (halfs)
#define CLD 264     // C smem row stride (floats)

#define A_STAGE 18432             // 128*72*2
#define B_STAGE 33792             // 64*264*2
#define STG (A_STAGE + B_STAGE)   // 52224
#define OFF_B A_STAGE
#define NSTAGE 3
#define SMEM_GEMM (NSTAGE * STG)  // 156672 (C tile 128*264*4=135168 aliases)
#define RLD 1028                  // router smem row stride (floats)
#define SMEM_ROUTER (16 * RLD * 4)
#define NCONV 512                 // conv blocks appended to router grid

__device__ __forceinline__ uint32_t smem_u32(const void* p) {
    uint32_t a;
    asm("{ .reg .u64 t; cvta.to.shared.u64 t, %1; cvt.u32.u64 %0, t; }" : "=r"(a) : "l"(p));
    return a;
}
#define CP_ASYNC16(dst, src, sz) \
    asm volatile("cp.async.cg.shared.global [%0], [%1], 16, %2;" \
                 :: "r"(dst), "l"(src), "r"(sz))
#define CP_COMMIT() asm volatile("cp.async.commit_group;")
#define CP_WAIT0()  asm volatile("cp.async.wait_group 0;")
#define CP_WAIT1()  asm volatile("cp.async.wait_group 1;")

// ---------------- scratch (device globals) ----------------
__device__ int   g_cnt[NEXP];
__device__ int   g_off[NEXP];
__device__ int   g_tok[NEXP * NTOK];
__device__ float g_gate[NEXP * NTOK];
__device__ __half g_xh[NTOK * DDIM];                 // fp16(x)
__device__ __half g_w1h[NEXP * DDIM * HDIM];         // fp16(W1)
__device__ __half g_w2h[NEXP * HDIM * ODIM];         // fp16(W2)
__device__ __half g_h[(size_t)NPAIR * HDIM];         // fp16(h)

// ---------------- router + fused fp16 conversions ----------------
// blocks [0, NTOK/16): routing + fp16(x) for 16 tokens each
// blocks [NTOK/16, NTOK/16+NCONV): fp16(W1), fp16(W2) grid-stride
__global__ void router_kernel(const float* __restrict__ x,
                              const float* __restrict__ noise,
                              const float* __restrict__ Wg,
                              const float* __restrict__ bg,
                              const float* __restrict__ Wn,
                              const float* __restrict__ bn,
                              const float4* __restrict__ W1,
                              const float4* __restrict__ W2) {
    extern __shared__ float Ws[];  // [16][RLD]
    int tid = threadIdx.x;
    int bx = blockIdx.x;
    if (bx >= NTOK / 16) {
        // weight conversion blocks
        const int n4 = NEXP * DDIM * HDIM / 4;
        int cid = bx - NTOK / 16;
        for (int i = cid * 256 + tid; i < 2 * n4; i += NCONV * 256) {
            bool second = i >= n4;
            int j = second ? i - n4 : i;
            float4 v = second ? W2[j] : W1[j];
            __half2* hi = (__half2*)(second ? g_w2h : g_w1h);
            hi[2 * j]     = __halves2half2(__float2half_rn(v.x), __float2half_rn(v.y));
            hi[2 * j + 1] = __halves2half2(__float2half_rn(v.z), __float2half_rn(v.w));
        }
        return;
    }
    for (int idx = tid; idx < DDIM * NEXP; idx += blockDim.x) {
        int k = idx >> 3, o = idx & 7;
        Ws[o * RLD + k]       = Wg[idx];
        Ws[(8 + o) * RLD + k] = Wn[idx];
    }
    __syncthreads();
    int warp = tid >> 5, lane = tid & 31;
    int o = lane & 15, half = lane >> 4;
    int t = bx * 16 + warp * 2 + half;

    const float4* xr = (const float4*)(x + (size_t)t * DDIM);
    const float4* wr = (const float4*)(Ws + o * RLD);
    float acc = 0.f;
#pragma unroll 8
    for (int k = 0; k < 256; ++k) {
        float4 xv = xr[k];
        float4 wv = wr[k];
        acc += xv.x * wv.x + xv.y * wv.y + xv.z * wv.z + xv.w * wv.w;
    }
    float nl_other = __shfl_sync(0xffffffffu, acc, (lane + 8) & 31);
    float noisy = -3.4e38f;
    if (o < 8) {
        float lg = acc + bg[o];
        float nl = nl_other + bn[o];
        float sp = nl > 20.f ? nl : log1pf(expf(nl));
        noisy = lg + noise[(size_t)t * 8 + o] * sp;
    }
    float v[8];
#pragma unroll
    for (int oo = 0; oo < 8; ++oo)
        v[oo] = __shfl_sync(0xffffffffu, noisy, (half << 4) + oo);
    if (o == 0) {
        int i1 = 0; float v1 = v[0];
#pragma unroll
        for (int oo = 1; oo < 8; ++oo) if (v[oo] > v1) { v1 = v[oo]; i1 = oo; }
        int i2 = 0; float v2 = -3.4e38f;
#pragma unroll
        for (int oo = 0; oo < 8; ++oo) if (oo != i1 && v[oo] > v2) { v2 = v[oo]; i2 = oo; }
        float ex = expf(v2 - v1);
        float inv = 1.f / (1.f + ex);
        int p1 = atomicAdd(&g_cnt[i1], 1);
        g_tok[i1 * NTOK + p1]  = t;
        g_gate[i1 * NTOK + p1] = inv;
        int p2 = atomicAdd(&g_cnt[i2], 1);
        g_tok[i2 * NTOK + p2]  = t;
        g_gate[i2 * NTOK + p2] = ex * inv;
    }
    // fused fp32->fp16 conversion of this block's 16 token rows
    int t0 = bx * 16;
    for (int i = tid; i < 16 * (DDIM / 4); i += blockDim.x) {
        int row = i >> 8, col = i & 255;
        float4 vx = *(const float4*)(x + (size_t)(t0 + row) * DDIM + col * 4);
        __half2* dst = (__half2*)(g_xh + (size_t)(t0 + row) * DDIM + col * 4);
        dst[0] = __halves2half2(__float2half_rn(vx.x), __float2half_rn(vx.y));
        dst[1] = __halves2half2(__float2half_rn(vx.z), __float2half_rn(vx.w));
    }
}

// ---------------- scan: expert offsets ----------------
__global__ void scan_kernel() {
    if (threadIdx.x == 0) {
        int s = 0;
#pragma unroll
        for (int e = 0; e < NEXP; ++e) { g_off[e] = s; s += g_cnt[e]; }
    }
}

// ---------------- grouped GEMM (R8 engine; gemm2 split-K x2) ----------------
// SECOND=false: h = relu(gather(xh) @ W1h[e] + b1[e]) -> g_h (fp16), KT=16
// SECOND=true : out += gate * (h @ W2h[e] [+ b2 on z=0]); K slice per blockIdx.z, KT=32
template <bool SECOND>
__global__ void __launch_bounds__(256, 1)
moe_gemm_kernel(const float* __restrict__ bias, float* __restrict__ out) {
    constexpr int NDIM = SECOND ? ODIM : HDIM;
    constexpr int KSLICE = SECOND ? (HDIM / 2) : DDIM;   // 2048 / 1024
    constexpr int KT = KSLICE / BK;                       // 32 / 16

    int e  = blockIdx.y >> 5;
    int mt = blockIdx.y & 31;
    int cnt = g_cnt[e];
    int m0 = mt * BM;
    if (m0 >= cnt) return;
    int off = g_off[e];
    int n0 = blockIdx.x * BN;
    int kbase = SECOND ? (int)(blockIdx.z * KSLICE) : 0;
    int tid = threadIdx.x;
    int w = tid >> 5;
    int wm = (w & 1) * 64, wn = (w >> 1) * 64;

    extern __shared__ __align__(128) char raw[];
    uint32_t sbase = smem_u32(raw);

    const __half* Asrc = SECOND ? g_h : g_xh;
    const __half* Bsrc = SECOND ? g_w2h : g_w1h;

    // A: chunk id = tid + 256*i (i<4): row = id>>3, c8 = id&7 (8 halfs = 16B)
    size_t asrc[4]; uint32_t asz[4]; uint32_t adst[4];
#pragma unroll
    for (int i = 0; i < 4; ++i) {
        int id = tid + 256 * i;
        int row = id >> 3, c8 = id & 7;
        int pos = m0 + row;
        bool aval = pos < cnt;
        asz[i] = aval ? 16u : 0u;
        if (SECOND) {
            asrc[i] = (size_t)(off + (aval ? pos : 0)) * HDIM + kbase + c8 * 8;
        } else {
            int token = aval ? g_tok[e * NTOK + pos] : 0;
            asrc[i] = (size_t)token * DDIM + c8 * 8;
        }
        adst[i] = sbase + row * (ALD * 2) + c8 * 16;
    }
    // B: chunk id = tid + 256*i (i<8): row = id>>5, c16 = id&31
    size_t bsrc[8]; uint32_t bdst[8];
#pragma unroll
    for (int i = 0; i < 8; ++i) {
        int id = tid + 256 * i;
        int row = id >> 5, c16 = id & 31;
        bsrc[i] = (size_t)e * (size_t)(SECOND ? HDIM * ODIM : DDIM * HDIM) +
                  (size_t)(kbase + row) * NDIM + n0 + c16 * 8;
        bdst[i] = sbase + OFF_B + row * (BLD * 2) + c16 * 16;
    }

    auto fill = [&](int s, int kt) {
        int ko = kt * BK;
        uint32_t sb = s * STG;
#pragma unroll
        for (int i = 0; i < 4; ++i)
            CP_ASYNC16(adst[i] + sb, (const char*)(Asrc + asrc[i] + ko), asz[i]);
        size_t kofs = (size_t)ko * NDIM;
#pragma unroll
        for (int i = 0; i < 8; ++i)
            CP_ASYNC16(bdst[i] + sb, (const char*)(Bsrc + bsrc[i] + kofs), 16u);
        CP_COMMIT();
    };

    wmma::fragment<wmma::accumulator, 16, 16, 16, float> acc[4][4];
#pragma unroll
    for (int i = 0; i < 4; ++i)
#pragma unroll
        for (int j = 0; j < 4; ++j) wmma::fill_fragment(acc[i][j], 0.f);

    auto compute = [&](int s) {
        const __half* Ah = (const __half*)(raw + s * STG);
        const __half* Bh = (const __half*)(raw + s * STG + OFF_B);
#pragma unroll
        for (int kk = 0; kk < BK; kk += 16) {
            wmma::fragment<wmma::matrix_a, 16, 16, 16, __half, wmma::row_major> fa[4];
            wmma::fragment<wmma::matrix_b, 16, 16, 16, __half, wmma::row_major> fb[4];
#pragma unroll
            for (int i = 0; i < 4; ++i)
                wmma::load_matrix_sync(fa[i], Ah + (wm + 16 * i) * ALD + kk, ALD);
#pragma unroll
            for (int j = 0; j < 4; ++j)
                wmma::load_matrix_sync(fb[j], Bh + kk * BLD + wn + 16 * j, BLD);
#pragma unroll
            for (int i = 0; i < 4; ++i)
#pragma unroll
                for (int j = 0; j < 4; ++j)
                    wmma::mma_sync(acc[i][j], fa[i], fb[j], acc[i][j]);
        }
    };

    fill(0, 0);
    fill(1, 1);
#pragma unroll 1
    for (int kt = 0; kt < KT; ++kt) {
        if (KT - kt >= 2) CP_WAIT1(); else CP_WAIT0();
        __syncthreads();
        if (kt + 2 < KT) fill((kt + 2) % NSTAGE, kt + 2);
        compute(kt % NSTAGE);
    }

    // epilogue via smem C tile (aliased over stage buffers)
    __syncthreads();
    float* sC = (float*)raw;
#pragma unroll
    for (int i = 0; i < 4; ++i)
#pragma unroll
        for (int j = 0; j < 4; ++j)
            wmma::store_matrix_sync(sC + (wm + 16 * i) * CLD + wn + 16 * j, acc[i][j], CLD,
                                    wmma::mem_row_major);
    __syncthreads();

    if (!SECOND) {
        for (int q = tid; q < BM * (BN / 8); q += 256) {
            int r = q >> 5;
            int c = (q & 31) * 8;
            int pos = m0 + r;
            if (pos >= cnt) continue;
            int nb = n0 + c;
            uint4 pk;
            __half2 p[4];
#pragma unroll
            for (int u = 0; u < 4; ++u) {
                float v0 = sC[r * CLD + c + 2 * u]     + bias[e * NDIM + nb + 2 * u];
                float v1 = sC[r * CLD + c + 2 * u + 1] + bias[e * NDIM + nb + 2 * u + 1];
                p[u] = __halves2half2(__float2half_rn(fmaxf(v0, 0.f)),
                                      __float2half_rn(fmaxf(v1, 0.f)));
            }
            pk.x = *(uint32_t*)&p[0]; pk.y = *(uint32_t*)&p[1];
            pk.z = *(uint32_t*)&p[2]; pk.w = *(uint32_t*)&p[3];
            *(uint4*)(g_h + (size_t)(off + pos) * HDIM + nb) = pk;
        }
    } else {
        bool add_bias = (blockIdx.z == 0);
        for (int q = tid; q < BM * (BN / 4); q += 256) {
            int r = q >> 6;
            int c = (q & 63) * 4;
            int pos = m0 + r;
            if (pos >= cnt) continue;
            float gate = g_gate[e * NTOK + pos];
            int token  = g_tok[e * NTOK + pos];
            int nb = n0 + c;
            float* op = out + (size_t)token * ODIM + nb;
#pragma unroll
            for (int u = 0; u < 4; ++u) {
                float v = sC[r * CLD + c + u];
                if (add_bias) v += bias[e * NDIM + nb + u];
                atomicAdd(op + u, v * gate);
            }
        }
    }
}

// ---------------- launch ----------------
extern "C" void kernel_launch(void* const* d_in, const int* in_sizes, int n_in,
                              void* d_out, int out_size) {
    const float* x     = (const float*)d_in[0];
    const float* noise = (const float*)d_in[1];
    const float* Wg    = (const float*)d_in[2];
    const float* bg    = (const float*)d_in[3];
    const float* Wn    = (const float*)d_in[4];
    const float* bn    = (const float*)d_in[5];
    const float* W1    = (const float*)d_in[6];
    const float* b1    = (const float*)d_in[7];
    const float* W2    = (const float*)d_in[8];
    const float* b2    = (const float*)d_in[9];
    (void)in_sizes; (void)n_in;

    void* cnt_ptr;
    cudaGetSymbolAddress(&cnt_ptr, g_cnt);

    cudaFuncSetAttribute(router_kernel, cudaFuncAttributeMaxDynamicSharedMemorySize, SMEM_ROUTER);
    cudaFuncSetAttribute(moe_gemm_kernel<false>, cudaFuncAttributeMaxDynamicSharedMemorySize, SMEM_GEMM);
    cudaFuncSetAttribute(moe_gemm_kernel<true>,  cudaFuncAttributeMaxDynamicSharedMemorySize, SMEM_GEMM);

    // launches: 0 memset cnt, 1 memset out, 2 router(+convs), 3 scan,
    //           4 gemm1, 5 gemm2 (profiled: ncu -s 5 -c 1)
    cudaMemsetAsync(cnt_ptr, 0, NEXP * sizeof(int));
    cudaMemsetAsync(d_out, 0, (size_t)out_size * sizeof(float));

    router_kernel<<<NTOK / 16 + NCONV, 256, SMEM_ROUTER>>>(
        x, noise, Wg, bg, Wn, bn, (const float4*)W1, (const float4*)W2);
    scan_kernel<<<1, 32>>>();

    moe_gemm_kernel<false><<<dim3(HDIM / BN, NEXP * 32, 1), 256, SMEM_GEMM>>>(b1, nullptr);
    moe_gemm_kernel<true> <<<dim3(ODIM / BN, NEXP * 32, 2), 256, SMEM_GEMM>>>(b2, (float*)d_out);
}

// round 15
// speedup vs baseline: 1.1403x; 1.0220x over previous
#include <cuda_runtime.h>
#include <cuda_fp16.h>
#include <mma.h>
#include <math.h>
#include <cstdint>

using namespace nvcuda;

#define NTOK 4096
#define DDIM 1024
#define HDIM 4096
#define ODIM 1024
#define NEXP 8
#define NPAIR 8192

#define BM 128
#define BN 256
#define BK 64
#define ALD 72      // A smem row stride (halfs)
#define BLD 264     // B smem row stride (halfs)
#define CLD 264     // C smem row stride (floats)

#define A_STAGE 18432             // 128*72*2
#define B_STAGE 33792             // 64*264*2
#define STG (A_STAGE + B_STAGE)   // 52224
#define OFF_B A_STAGE
#define NSTAGE 3
#define SMEM_GEMM (NSTAGE * STG)  // 156672 (C tile 128*264*4=135168 aliases)
#define RLD 1028                  // router smem row stride (floats)
#define SMEM_ROUTER (16 * RLD * 4)

__device__ __forceinline__ uint32_t smem_u32(const void* p) {
    uint32_t a;
    asm("{ .reg .u64 t; cvta.to.shared.u64 t, %1; cvt.u32.u64 %0, t; }" : "=r"(a) : "l"(p));
    return a;
}
#define CP_ASYNC16(dst, src, sz) \
    asm volatile("cp.async.cg.shared.global [%0], [%1], 16, %2;" \
                 :: "r"(dst), "l"(src), "r"(sz))
#define CP_COMMIT() asm volatile("cp.async.commit_group;")
#define CP_WAIT0()  asm volatile("cp.async.wait_group 0;")
#define CP_WAIT1()  asm volatile("cp.async.wait_group 1;")

// ---------------- scratch (device globals) ----------------
__device__ int   g_cnt[NEXP];
__device__ int   g_off[NEXP];
__device__ int   g_tok[NEXP * NTOK];
// per-token routing record: for token t, slots 2t / 2t+1
__device__ int   g_ti[2 * NTOK];     // expert index
__device__ int   g_tp[2 * NTOK];     // position within expert list
__device__ float g_tg[2 * NTOK];     // gate
__device__ __half g_xh[NTOK * DDIM];                 // fp16(x)
__device__ __half g_w1h[NEXP * DDIM * HDIM];         // fp16(W1)
__device__ __half g_w2h[NEXP * HDIM * ODIM];         // fp16(W2)
__device__ __half g_h[(size_t)NPAIR * HDIM];         // fp16(h)
__device__ float  g_ct[(size_t)NPAIR * ODIM];        // gemm2 contributions

// ---------------- W1 + W2: fp32 -> fp16 ----------------
__global__ void conv_w_kernel(const float4* __restrict__ W1,
                              const float4* __restrict__ W2) {
    const int n4 = NEXP * DDIM * HDIM / 4;
    int i = blockIdx.x * blockDim.x + threadIdx.x;
    if (i >= 2 * n4) return;
    bool second = i >= n4;
    int j = second ? i - n4 : i;
    float4 v = second ? W2[j] : W1[j];
    __half2* hi = (__half2*)(second ? g_w2h : g_w1h);
    hi[2 * j]     = __halves2half2(__float2half_rn(v.x), __float2half_rn(v.y));
    hi[2 * j + 1] = __halves2half2(__float2half_rn(v.z), __float2half_rn(v.w));
}

// ---------------- router: expert-per-lane, 2 tokens/warp; also emits fp16(x) ----------------
__global__ void router_kernel(const float* __restrict__ x,
                              const float* __restrict__ noise,
                              const float* __restrict__ Wg,
                              const float* __restrict__ bg,
                              const float* __restrict__ Wn,
                              const float* __restrict__ bn) {
    extern __shared__ float Ws[];  // [16][RLD] rows: 0..7 Wg cols, 8..15 Wn cols
    int tid = threadIdx.x;
    for (int idx = tid; idx < DDIM * NEXP; idx += blockDim.x) {
        int k = idx >> 3, o = idx & 7;
        Ws[o * RLD + k]       = Wg[idx];
        Ws[(8 + o) * RLD + k] = Wn[idx];
    }
    __syncthreads();
    int warp = tid >> 5, lane = tid & 31;
    int o = lane & 15, half = lane >> 4;
    int t = blockIdx.x * 16 + warp * 2 + half;

    const float4* xr = (const float4*)(x + (size_t)t * DDIM);
    const float4* wr = (const float4*)(Ws + o * RLD);
    float acc = 0.f;
#pragma unroll 8
    for (int k = 0; k < 256; ++k) {
        float4 xv = xr[k];
        float4 wv = wr[k];
        acc += xv.x * wv.x + xv.y * wv.y + xv.z * wv.z + xv.w * wv.w;
    }
    float nl_other = __shfl_sync(0xffffffffu, acc, (lane + 8) & 31);
    float noisy = -3.4e38f;
    if (o < 8) {
        float lg = acc + bg[o];
        float nl = nl_other + bn[o];
        float sp = nl > 20.f ? nl : log1pf(expf(nl));
        noisy = lg + noise[(size_t)t * 8 + o] * sp;
    }
    float v[8];
#pragma unroll
    for (int oo = 0; oo < 8; ++oo)
        v[oo] = __shfl_sync(0xffffffffu, noisy, (half << 4) + oo);
    if (o == 0) {
        int i1 = 0; float v1 = v[0];
#pragma unroll
        for (int oo = 1; oo < 8; ++oo) if (v[oo] > v1) { v1 = v[oo]; i1 = oo; }
        int i2 = 0; float v2 = -3.4e38f;
#pragma unroll
        for (int oo = 0; oo < 8; ++oo) if (oo != i1 && v[oo] > v2) { v2 = v[oo]; i2 = oo; }
        float ex = expf(v2 - v1);
        float inv = 1.f / (1.f + ex);
        float gg2 = ex * inv;
        int p1 = atomicAdd(&g_cnt[i1], 1);
        g_tok[i1 * NTOK + p1] = t;
        int p2 = atomicAdd(&g_cnt[i2], 1);
        g_tok[i2 * NTOK + p2] = t;
        g_ti[2 * t] = i1;  g_tp[2 * t] = p1;  g_tg[2 * t] = inv;
        g_ti[2 * t + 1] = i2;  g_tp[2 * t + 1] = p2;  g_tg[2 * t + 1] = gg2;
    }
    // fused fp32->fp16 conversion of this block's 16 token rows (L1/L2 hot)
    int t0 = blockIdx.x * 16;
    for (int i = tid; i < 16 * (DDIM / 4); i += blockDim.x) {
        int row = i >> 8, col = i & 255;
        float4 vx = *(const float4*)(x + (size_t)(t0 + row) * DDIM + col * 4);
        __half2* dst = (__half2*)(g_xh + (size_t)(t0 + row) * DDIM + col * 4);
        dst[0] = __halves2half2(__float2half_rn(vx.x), __float2half_rn(vx.y));
        dst[1] = __halves2half2(__float2half_rn(vx.z), __float2half_rn(vx.w));
    }
}

// ---------------- scan: expert offsets ----------------
__global__ void scan_kernel() {
    if (threadIdx.x == 0) {
        int s = 0;
#pragma unroll
        for (int e = 0; e < NEXP; ++e) { g_off[e] = s; s += g_cnt[e]; }
    }
}

// ---------------- grouped GEMM (R8 engine, unchanged mainloop) ----------------
// SECOND=false: h = relu(gather(xh) @ W1h[e] + b1[e]) -> g_h (fp16)
// SECOND=true : g_ct[row] = h @ W2h[e]   (plain stores; bias+gate applied in combine)
template <bool SECOND>
__global__ void __launch_bounds__(256, 1)
moe_gemm_kernel(const float* __restrict__ bias) {
    constexpr int KDIM = SECOND ? HDIM : DDIM;
    constexpr int NDIM = SECOND ? ODIM : HDIM;
    constexpr int KT = KDIM / BK;

    int e  = blockIdx.y >> 5;
    int mt = blockIdx.y & 31;
    int cnt = g_cnt[e];
    int m0 = mt * BM;
    if (m0 >= cnt) return;
    int off = g_off[e];
    int n0 = blockIdx.x * BN;
    int tid = threadIdx.x;
    int w = tid >> 5;
    int wm = (w & 1) * 64, wn = (w >> 1) * 64;

    extern __shared__ __align__(128) char raw[];
    uint32_t sbase = smem_u32(raw);

    const __half* Asrc = SECOND ? g_h : g_xh;
    const __half* Bsrc = SECOND ? g_w2h : g_w1h;

    // A: chunk id = tid + 256*i (i<4): row = id>>3, c8 = id&7 (8 halfs = 16B)
    size_t asrc[4]; uint32_t asz[4]; uint32_t adst[4];
#pragma unroll
    for (int i = 0; i < 4; ++i) {
        int id = tid + 256 * i;
        int row = id >> 3, c8 = id & 7;
        int pos = m0 + row;
        bool aval = pos < cnt;
        asz[i] = aval ? 16u : 0u;
        if (SECOND) {
            asrc[i] = (size_t)(off + (aval ? pos : 0)) * HDIM + c8 * 8;
        } else {
            int token = aval ? g_tok[e * NTOK + pos] : 0;
            asrc[i] = (size_t)token * DDIM + c8 * 8;
        }
        adst[i] = sbase + row * (ALD * 2) + c8 * 16;
    }
    // B: chunk id = tid + 256*i (i<8): row = id>>5, c16 = id&31
    size_t bsrc[8]; uint32_t bdst[8];
#pragma unroll
    for (int i = 0; i < 8; ++i) {
        int id = tid + 256 * i;
        int row = id >> 5, c16 = id & 31;
        bsrc[i] = (size_t)e * KDIM * NDIM + (size_t)row * NDIM + n0 + c16 * 8;
        bdst[i] = sbase + OFF_B + row * (BLD * 2) + c16 * 16;
    }

    auto fill = [&](int s, int kt) {
        int ko = kt * BK;
        uint32_t sb = s * STG;
#pragma unroll
        for (int i = 0; i < 4; ++i)
            CP_ASYNC16(adst[i] + sb, (const char*)(Asrc + asrc[i] + ko), asz[i]);
        size_t kofs = (size_t)ko * NDIM;
#pragma unroll
        for (int i = 0; i < 8; ++i)
            CP_ASYNC16(bdst[i] + sb, (const char*)(Bsrc + bsrc[i] + kofs), 16u);
        CP_COMMIT();
    };

    wmma::fragment<wmma::accumulator, 16, 16, 16, float> acc[4][4];
#pragma unroll
    for (int i = 0; i < 4; ++i)
#pragma unroll
        for (int j = 0; j < 4; ++j) wmma::fill_fragment(acc[i][j], 0.f);

    auto compute = [&](int s) {
        const __half* Ah = (const __half*)(raw + s * STG);
        const __half* Bh = (const __half*)(raw + s * STG + OFF_B);
#pragma unroll
        for (int kk = 0; kk < BK; kk += 16) {
            wmma::fragment<wmma::matrix_a, 16, 16, 16, __half, wmma::row_major> fa[4];
            wmma::fragment<wmma::matrix_b, 16, 16, 16, __half, wmma::row_major> fb[4];
#pragma unroll
            for (int i = 0; i < 4; ++i)
                wmma::load_matrix_sync(fa[i], Ah + (wm + 16 * i) * ALD + kk, ALD);
#pragma unroll
            for (int j = 0; j < 4; ++j)
                wmma::load_matrix_sync(fb[j], Bh + kk * BLD + wn + 16 * j, BLD);
#pragma unroll
            for (int i = 0; i < 4; ++i)
#pragma unroll
                for (int j = 0; j < 4; ++j)
                    wmma::mma_sync(acc[i][j], fa[i], fb[j], acc[i][j]);
        }
    };

    fill(0, 0);
    fill(1, 1);
#pragma unroll 1
    for (int kt = 0; kt < KT; ++kt) {
        if (KT - kt >= 2) CP_WAIT1(); else CP_WAIT0();
        __syncthreads();
        if (kt + 2 < KT) fill((kt + 2) % NSTAGE, kt + 2);
        compute(kt % NSTAGE);
    }

    // epilogue via smem C tile (aliased over stage buffers)
    __syncthreads();
    float* sC = (float*)raw;
#pragma unroll
    for (int i = 0; i < 4; ++i)
#pragma unroll
        for (int j = 0; j < 4; ++j)
            wmma::store_matrix_sync(sC + (wm + 16 * i) * CLD + wn + 16 * j, acc[i][j], CLD,
                                    wmma::mem_row_major);
    __syncthreads();

    if (!SECOND) {
        for (int q = tid; q < BM * (BN / 8); q += 256) {
            int r = q >> 5;
            int c = (q & 31) * 8;
            int pos = m0 + r;
            if (pos >= cnt) continue;
            int nb = n0 + c;
            uint4 pk;
            __half2 p[4];
#pragma unroll
            for (int u = 0; u < 4; ++u) {
                float v0 = sC[r * CLD + c + 2 * u]     + bias[e * NDIM + nb + 2 * u];
                float v1 = sC[r * CLD + c + 2 * u + 1] + bias[e * NDIM + nb + 2 * u + 1];
                p[u] = __halves2half2(__float2half_rn(fmaxf(v0, 0.f)),
                                      __float2half_rn(fmaxf(v1, 0.f)));
            }
            pk.x = *(uint32_t*)&p[0]; pk.y = *(uint32_t*)&p[1];
            pk.z = *(uint32_t*)&p[2]; pk.w = *(uint32_t*)&p[3];
            *(uint4*)(g_h + (size_t)(off + pos) * HDIM + nb) = pk;
        }
    } else {
        // plain stores of raw contributions (bias/gate applied in combine kernel)
        for (int q = tid; q < BM * (BN / 8); q += 256) {
            int r = q >> 5;
            int c = (q & 31) * 8;
            int pos = m0 + r;
            if (pos >= cnt) continue;
            int nb = n0 + c;
            float* dst = g_ct + (size_t)(off + pos) * ODIM + nb;
            float4 v0 = *(float4*)(sC + r * CLD + c);
            float4 v1 = *(float4*)(sC + r * CLD + c + 4);
            *(float4*)(dst)     = v0;
            *(float4*)(dst + 4) = v1;
        }
    }
}

// ---------------- combine: out[t] = g1*(c[r1]+b2[e1]) + g2*(c[r2]+b2[e2]) ----------------
__global__ void combine_kernel(const float* __restrict__ b2, float4* __restrict__ out) {
    int t = blockIdx.x, tid = threadIdx.x;
    __shared__ int s_r1, s_r2, s_e1, s_e2;
    __shared__ float s_g1, s_g2;
    if (tid == 0) {
        int e1 = g_ti[2 * t], e2 = g_ti[2 * t + 1];
        s_e1 = e1; s_e2 = e2;
        s_r1 = g_off[e1] + g_tp[2 * t];
        s_r2 = g_off[e2] + g_tp[2 * t + 1];
        s_g1 = g_tg[2 * t];
        s_g2 = g_tg[2 * t + 1];
    }
    __syncthreads();
    const float4* c1 = (const float4*)(g_ct + (size_t)s_r1 * ODIM);
    const float4* c2 = (const float4*)(g_ct + (size_t)s_r2 * ODIM);
    const float4* bb1 = (const float4*)(b2 + s_e1 * ODIM);
    const float4* bb2 = (const float4*)(b2 + s_e2 * ODIM);
    float g1 = s_g1, g2 = s_g2;
    float4 a = c1[tid], b = c2[tid], x1 = bb1[tid], x2 = bb2[tid];
    float4 o;
    o.x = g1 * (a.x + x1.x) + g2 * (b.x + x2.x);
    o.y = g1 * (a.y + x1.y) + g2 * (b.y + x2.y);
    o.z = g1 * (a.z + x1.z) + g2 * (b.z + x2.z);
    o.w = g1 * (a.w + x1.w) + g2 * (b.w + x2.w);
    out[(size_t)t * (ODIM / 4) + tid] = o;
}

// ---------------- launch ----------------
extern "C" void kernel_launch(void* const* d_in, const int* in_sizes, int n_in,
                              void* d_out, int out_size) {
    const float* x     = (const float*)d_in[0];
    const float* noise = (const float*)d_in[1];
    const float* Wg    = (const float*)d_in[2];
    const float* bg    = (const float*)d_in[3];
    const float* Wn    = (const float*)d_in[4];
    const float* bn    = (const float*)d_in[5];
    const float* W1    = (const float*)d_in[6];
    const float* b1    = (const float*)d_in[7];
    const float* W2    = (const float*)d_in[8];
    const float* b2    = (const float*)d_in[9];
    (void)in_sizes; (void)n_in; (void)out_size;

    void* cnt_ptr;
    cudaGetSymbolAddress(&cnt_ptr, g_cnt);

    cudaFuncSetAttribute(router_kernel, cudaFuncAttributeMaxDynamicSharedMemorySize, SMEM_ROUTER);
    cudaFuncSetAttribute(moe_gemm_kernel<false>, cudaFuncAttributeMaxDynamicSharedMemorySize, SMEM_GEMM);
    cudaFuncSetAttribute(moe_gemm_kernel<true>,  cudaFuncAttributeMaxDynamicSharedMemorySize, SMEM_GEMM);

    // launches: 0 memset cnt, 1 router(+conv_x), 2 conv_w, 3 scan,
    //           4 gemm1, 5 gemm2 (profiled: ncu -s 5 -c 1), 6 combine
    cudaMemsetAsync(cnt_ptr, 0, NEXP * sizeof(int));

    router_kernel<<<NTOK / 16, 256, SMEM_ROUTER>>>(x, noise, Wg, bg, Wn, bn);
    int n4w = NEXP * DDIM * HDIM / 4;
    conv_w_kernel<<<(2 * n4w + 255) / 256, 256>>>((const float4*)W1, (const float4*)W2);
    scan_kernel<<<1, 32>>>();

    moe_gemm_kernel<false><<<dim3(HDIM / BN, NEXP * 32), 256, SMEM_GEMM>>>(b1);
    moe_gemm_kernel<true> <<<dim3(ODIM / BN, NEXP * 32), 256, SMEM_GEMM>>>(nullptr);
    combine_kernel<<<NTOK, 256>>>(b2, (float4*)d_out);
}

// round 16
// speedup vs baseline: 1.1736x; 1.0292x over previous
#include <cuda_runtime.h>
#include <cuda_fp16.h>
#include <mma.h>
#include <math.h>
#include <cstdint>

using namespace nvcuda;

#define NTOK 4096
#define DDIM 1024
#define HDIM 4096
#define ODIM 1024
#define NEXP 8
#define NPAIR 8192

#define BM 128
#define BN 256
#define BK 64
#define ALD 72      // A smem row stride (halfs)
#define BLD 264     // B smem row stride (halfs)
#define CLD 264     // C smem row stride (floats)

#define A_STAGE 18432             // 128*72*2
#define B_STAGE 33792             // 64*264*2
#define STG (A_STAGE + B_STAGE)   // 52224
#define OFF_B A_STAGE
#define NSTAGE 3
#define SMEM_GEMM (NSTAGE * STG)  // 156672 (C tile 128*264*4=135168 aliases)
#define RLD 1028                  // router smem row stride (floats)
#define SMEM_ROUTER (16 * RLD * 4)

__device__ __forceinline__ uint32_t smem_u32(const void* p) {
    uint32_t a;
    asm("{ .reg .u64 t; cvta.to.shared.u64 t, %1; cvt.u32.u64 %0, t; }" : "=r"(a) : "l"(p));
    return a;
}
#define CP_ASYNC16(dst, src, sz) \
    asm volatile("cp.async.cg.shared.global [%0], [%1], 16, %2;" \
                 :: "r"(dst), "l"(src), "r"(sz))
#define CP_COMMIT() asm volatile("cp.async.commit_group;")
#define CP_WAIT0()  asm volatile("cp.async.wait_group 0;")
#define CP_WAIT1()  asm volatile("cp.async.wait_group 1;")

// ---------------- scratch (device globals) ----------------
__device__ int   g_cnt[NEXP];
__device__ int   g_tok[NEXP * NTOK];
// per-token routing record: for token t, slots 2t / 2t+1
__device__ int   g_ti[2 * NTOK];     // expert index
__device__ int   g_tp[2 * NTOK];     // position within expert list
__device__ float g_tg[2 * NTOK];     // gate
__device__ __half g_xh[NTOK * DDIM];                 // fp16(x)
__device__ __half g_w1h[NEXP * DDIM * HDIM];         // fp16(W1)
__device__ __half g_w2h[NEXP * HDIM * ODIM];         // fp16(W2)
__device__ __half g_h[(size_t)NPAIR * HDIM];         // fp16(h)
__device__ float  g_ct[(size_t)NPAIR * ODIM];        // gemm2 contributions

// ---------------- router + fused conversions (x and a W stripe per block) ----------------
__global__ void router_kernel(const float* __restrict__ x,
                              const float* __restrict__ noise,
                              const float* __restrict__ Wg,
                              const float* __restrict__ bg,
                              const float* __restrict__ Wn,
                              const float* __restrict__ bn,
                              const float4* __restrict__ W1,
                              const float4* __restrict__ W2) {
    extern __shared__ float Ws[];  // [16][RLD] rows: 0..7 Wg cols, 8..15 Wn cols
    int tid = threadIdx.x;
    for (int idx = tid; idx < DDIM * NEXP; idx += blockDim.x) {
        int k = idx >> 3, o = idx & 7;
        Ws[o * RLD + k]       = Wg[idx];
        Ws[(8 + o) * RLD + k] = Wn[idx];
    }
    __syncthreads();
    int warp = tid >> 5, lane = tid & 31;
    int o = lane & 15, half = lane >> 4;
    int t = blockIdx.x * 16 + warp * 2 + half;

    const float4* xr = (const float4*)(x + (size_t)t * DDIM);
    const float4* wr = (const float4*)(Ws + o * RLD);
    float acc = 0.f;
#pragma unroll 8
    for (int k = 0; k < 256; ++k) {
        float4 xv = xr[k];
        float4 wv = wr[k];
        acc += xv.x * wv.x + xv.y * wv.y + xv.z * wv.z + xv.w * wv.w;
    }
    float nl_other = __shfl_sync(0xffffffffu, acc, (lane + 8) & 31);
    float noisy = -3.4e38f;
    if (o < 8) {
        float lg = acc + bg[o];
        float nl = nl_other + bn[o];
        float sp = nl > 20.f ? nl : log1pf(expf(nl));
        noisy = lg + noise[(size_t)t * 8 + o] * sp;
    }
    float v[8];
#pragma unroll
    for (int oo = 0; oo < 8; ++oo)
        v[oo] = __shfl_sync(0xffffffffu, noisy, (half << 4) + oo);
    if (o == 0) {
        int i1 = 0; float v1 = v[0];
#pragma unroll
        for (int oo = 1; oo < 8; ++oo) if (v[oo] > v1) { v1 = v[oo]; i1 = oo; }
        int i2 = 0; float v2 = -3.4e38f;
#pragma unroll
        for (int oo = 0; oo < 8; ++oo) if (oo != i1 && v[oo] > v2) { v2 = v[oo]; i2 = oo; }
        float ex = expf(v2 - v1);
        float inv = 1.f / (1.f + ex);
        float gg2 = ex * inv;
        int p1 = atomicAdd(&g_cnt[i1], 1);
        g_tok[i1 * NTOK + p1] = t;
        int p2 = atomicAdd(&g_cnt[i2], 1);
        g_tok[i2 * NTOK + p2] = t;
        g_ti[2 * t] = i1;  g_tp[2 * t] = p1;  g_tg[2 * t] = inv;
        g_ti[2 * t + 1] = i2;  g_tp[2 * t + 1] = p2;  g_tg[2 * t + 1] = gg2;
    }
    // fused fp32->fp16 conversion of this block's 16 token rows (L1/L2 hot)
    int t0 = blockIdx.x * 16;
    for (int i = tid; i < 16 * (DDIM / 4); i += blockDim.x) {
        int row = i >> 8, col = i & 255;
        float4 vx = *(const float4*)(x + (size_t)(t0 + row) * DDIM + col * 4);
        __half2* dst = (__half2*)(g_xh + (size_t)(t0 + row) * DDIM + col * 4);
        dst[0] = __halves2half2(__float2half_rn(vx.x), __float2half_rn(vx.y));
        dst[1] = __halves2half2(__float2half_rn(vx.z), __float2half_rn(vx.w));
    }
    // fused W1/W2 fp32->fp16: each of the 256 blocks converts a contiguous
    // 65536-float4 stripe (blocks 0..127 -> W1, 128..255 -> W2)
    {
        const int n4 = NEXP * DDIM * HDIM / 4;           // 8388608
        const int stripe = 2 * n4 / (NTOK / 16);         // 65536
        size_t base = (size_t)blockIdx.x * stripe;
        bool second = base >= (size_t)n4;
        size_t j0 = second ? base - n4 : base;
        const float4* src = second ? W2 : W1;
        __half2* hi = (__half2*)(second ? g_w2h : g_w1h);
#pragma unroll 4
        for (int i = tid; i < stripe; i += 256) {
            size_t j = j0 + i;
            float4 vv = src[j];
            hi[2 * j]     = __halves2half2(__float2half_rn(vv.x), __float2half_rn(vv.y));
            hi[2 * j + 1] = __halves2half2(__float2half_rn(vv.z), __float2half_rn(vv.w));
        }
    }
}

// ---------------- grouped GEMM (R8 engine, unchanged mainloop) ----------------
// SECOND=false: h = relu(gather(xh) @ W1h[e] + b1[e]) -> g_h (fp16)
// SECOND=true : g_ct[row] = h @ W2h[e]   (plain stores; bias+gate applied in combine)
template <bool SECOND>
__global__ void __launch_bounds__(256, 1)
moe_gemm_kernel(const float* __restrict__ bias) {
    constexpr int KDIM = SECOND ? HDIM : DDIM;
    constexpr int NDIM = SECOND ? ODIM : HDIM;
    constexpr int KT = KDIM / BK;

    int e  = blockIdx.y >> 5;
    int mt = blockIdx.y & 31;
    int cnt = g_cnt[e];
    int m0 = mt * BM;
    if (m0 >= cnt) return;
    int off = 0;
#pragma unroll
    for (int q = 0; q < NEXP; ++q) off += (q < e) ? g_cnt[q] : 0;
    int n0 = blockIdx.x * BN;
    int tid = threadIdx.x;
    int w = tid >> 5;
    int wm = (w & 1) * 64, wn = (w >> 1) * 64;

    extern __shared__ __align__(128) char raw[];
    uint32_t sbase = smem_u32(raw);

    const __half* Asrc = SECOND ? g_h : g_xh;
    const __half* Bsrc = SECOND ? g_w2h : g_w1h;

    // A: chunk id = tid + 256*i (i<4): row = id>>3, c8 = id&7 (8 halfs = 16B)
    size_t asrc[4]; uint32_t asz[4]; uint32_t adst[4];
#pragma unroll
    for (int i = 0; i < 4; ++i) {
        int id = tid + 256 * i;
        int row = id >> 3, c8 = id & 7;
        int pos = m0 + row;
        bool aval = pos < cnt;
        asz[i] = aval ? 16u : 0u;
        if (SECOND) {
            asrc[i] = (size_t)(off + (aval ? pos : 0)) * HDIM + c8 * 8;
        } else {
            int token = aval ? g_tok[e * NTOK + pos] : 0;
            asrc[i] = (size_t)token * DDIM + c8 * 8;
        }
        adst[i] = sbase + row * (ALD * 2) + c8 * 16;
    }
    // B: chunk id = tid + 256*i (i<8): row = id>>5, c16 = id&31
    size_t bsrc[8]; uint32_t bdst[8];
#pragma unroll
    for (int i = 0; i < 8; ++i) {
        int id = tid + 256 * i;
        int row = id >> 5, c16 = id & 31;
        bsrc[i] = (size_t)e * KDIM * NDIM + (size_t)row * NDIM + n0 + c16 * 8;
        bdst[i] = sbase + OFF_B + row * (BLD * 2) + c16 * 16;
    }

    auto fill = [&](int s, int kt) {
        int ko = kt * BK;
        uint32_t sb = s * STG;
#pragma unroll
        for (int i = 0; i < 4; ++i)
            CP_ASYNC16(adst[i] + sb, (const char*)(Asrc + asrc[i] + ko), asz[i]);
        size_t kofs = (size_t)ko * NDIM;
#pragma unroll
        for (int i = 0; i < 8; ++i)
            CP_ASYNC16(bdst[i] + sb, (const char*)(Bsrc + bsrc[i] + kofs), 16u);
        CP_COMMIT();
    };

    wmma::fragment<wmma::accumulator, 16, 16, 16, float> acc[4][4];
#pragma unroll
    for (int i = 0; i < 4; ++i)
#pragma unroll
        for (int j = 0; j < 4; ++j) wmma::fill_fragment(acc[i][j], 0.f);

    auto compute = [&](int s) {
        const __half* Ah = (const __half*)(raw + s * STG);
        const __half* Bh = (const __half*)(raw + s * STG + OFF_B);
#pragma unroll
        for (int kk = 0; kk < BK; kk += 16) {
            wmma::fragment<wmma::matrix_a, 16, 16, 16, __half, wmma::row_major> fa[4];
            wmma::fragment<wmma::matrix_b, 16, 16, 16, __half, wmma::row_major> fb[4];
#pragma unroll
            for (int i = 0; i < 4; ++i)
                wmma::load_matrix_sync(fa[i], Ah + (wm + 16 * i) * ALD + kk, ALD);
#pragma unroll
            for (int j = 0; j < 4; ++j)
                wmma::load_matrix_sync(fb[j], Bh + kk * BLD + wn + 16 * j, BLD);
#pragma unroll
            for (int i = 0; i < 4; ++i)
#pragma unroll
                for (int j = 0; j < 4; ++j)
                    wmma::mma_sync(acc[i][j], fa[i], fb[j], acc[i][j]);
        }
    };

    fill(0, 0);
    fill(1, 1);
#pragma unroll 1
    for (int kt = 0; kt < KT; ++kt) {
        if (KT - kt >= 2) CP_WAIT1(); else CP_WAIT0();
        __syncthreads();
        if (kt + 2 < KT) fill((kt + 2) % NSTAGE, kt + 2);
        compute(kt % NSTAGE);
    }

    // epilogue via smem C tile (aliased over stage buffers)
    __syncthreads();
    float* sC = (float*)raw;
#pragma unroll
    for (int i = 0; i < 4; ++i)
#pragma unroll
        for (int j = 0; j < 4; ++j)
            wmma::store_matrix_sync(sC + (wm + 16 * i) * CLD + wn + 16 * j, acc[i][j], CLD,
                                    wmma::mem_row_major);
    __syncthreads();

    if (!SECOND) {
        for (int q = tid; q < BM * (BN / 8); q += 256) {
            int r = q >> 5;
            int c = (q & 31) * 8;
            int pos = m0 + r;
            if (pos >= cnt) continue;
            int nb = n0 + c;
            uint4 pk;
            __half2 p[4];
#pragma unroll
            for (int u = 0; u < 4; ++u) {
                float v0 = sC[r * CLD + c + 2 * u]     + bias[e * NDIM + nb + 2 * u];
                float v1 = sC[r * CLD + c + 2 * u + 1] + bias[e * NDIM + nb + 2 * u + 1];
                p[u] = __halves2half2(__float2half_rn(fmaxf(v0, 0.f)),
                                      __float2half_rn(fmaxf(v1, 0.f)));
            }
            pk.x = *(uint32_t*)&p[0]; pk.y = *(uint32_t*)&p[1];
            pk.z = *(uint32_t*)&p[2]; pk.w = *(uint32_t*)&p[3];
            *(uint4*)(g_h + (size_t)(off + pos) * HDIM + nb) = pk;
        }
    } else {
        // plain stores of raw contributions (bias/gate applied in combine kernel)
        for (int q = tid; q < BM * (BN / 8); q += 256) {
            int r = q >> 5;
            int c = (q & 31) * 8;
            int pos = m0 + r;
            if (pos >= cnt) continue;
            int nb = n0 + c;
            float* dst = g_ct + (size_t)(off + pos) * ODIM + nb;
            float4 v0 = *(float4*)(sC + r * CLD + c);
            float4 v1 = *(float4*)(sC + r * CLD + c + 4);
            *(float4*)(dst)     = v0;
            *(float4*)(dst + 4) = v1;
        }
    }
}

// ---------------- combine: out[t] = g1*(c[r1]+b2[e1]) + g2*(c[r2]+b2[e2]) ----------------
__global__ void combine_kernel(const float* __restrict__ b2, float4* __restrict__ out) {
    int t = blockIdx.x, tid = threadIdx.x;
    __shared__ int s_r1, s_r2, s_e1, s_e2;
    __shared__ float s_g1, s_g2;
    if (tid == 0) {
        int e1 = g_ti[2 * t], e2 = g_ti[2 * t + 1];
        int off1 = 0, off2 = 0;
#pragma unroll
        for (int q = 0; q < NEXP; ++q) {
            int c = g_cnt[q];
            off1 += (q < e1) ? c : 0;
            off2 += (q < e2) ? c : 0;
        }
        s_e1 = e1; s_e2 = e2;
        s_r1 = off1 + g_tp[2 * t];
        s_r2 = off2 + g_tp[2 * t + 1];
        s_g1 = g_tg[2 * t];
        s_g2 = g_tg[2 * t + 1];
    }
    __syncthreads();
    const float4* c1 = (const float4*)(g_ct + (size_t)s_r1 * ODIM);
    const float4* c2 = (const float4*)(g_ct + (size_t)s_r2 * ODIM);
    const float4* bb1 = (const float4*)(b2 + s_e1 * ODIM);
    const float4* bb2 = (const float4*)(b2 + s_e2 * ODIM);
    float g1 = s_g1, g2 = s_g2;
    float4 a = c1[tid], b = c2[tid], x1 = bb1[tid], x2 = bb2[tid];
    float4 o;
    o.x = g1 * (a.x + x1.x) + g2 * (b.x + x2.x);
    o.y = g1 * (a.y + x1.y) + g2 * (b.y + x2.y);
    o.z = g1 * (a.z + x1.z) + g2 * (b.z + x2.z);
    o.w = g1 * (a.w + x1.w) + g2 * (b.w + x2.w);
    out[(size_t)t * (ODIM / 4) + tid] = o;
}

// ---------------- launch ----------------
extern "C" void kernel_launch(void* const* d_in, const int* in_sizes, int n_in,
                              void* d_out, int out_size) {
    const float* x     = (const float*)d_in[0];
    const float* noise = (const float*)d_in[1];
    const float* Wg    = (const float*)d_in[2];
    const float* bg    = (const float*)d_in[3];
    const float* Wn    = (const float*)d_in[4];
    const float* bn    = (const float*)d_in[5];
    const float* W1    = (const float*)d_in[6];
    const float* b1    = (const float*)d_in[7];
    const float* W2    = (const float*)d_in[8];
    const float* b2    = (const float*)d_in[9];
    (void)in_sizes; (void)n_in; (void)out_size;

    void* cnt_ptr;
    cudaGetSymbolAddress(&cnt_ptr, g_cnt);

    cudaFuncSetAttribute(router_kernel, cudaFuncAttributeMaxDynamicSharedMemorySize, SMEM_ROUTER);
    cudaFuncSetAttribute(moe_gemm_kernel<false>, cudaFuncAttributeMaxDynamicSharedMemorySize, SMEM_GEMM);
    cudaFuncSetAttribute(moe_gemm_kernel<true>,  cudaFuncAttributeMaxDynamicSharedMemorySize, SMEM_GEMM);

    // launches: 0 memset cnt, 1 router(+conv_x+conv_w), 2 gemm1, 3 gemm2, 4 combine
    cudaMemsetAsync(cnt_ptr, 0, NEXP * sizeof(int));

    router_kernel<<<NTOK / 16, 256, SMEM_ROUTER>>>(x, noise, Wg, bg, Wn, bn,
                                                   (const float4*)W1, (const float4*)W2);

    moe_gemm_kernel<false><<<dim3(HDIM / BN, NEXP * 32), 256, SMEM_GEMM>>>(b1);
    moe_gemm_kernel<true> <<<dim3(ODIM / BN, NEXP * 32), 256, SMEM_GEMM>>>(nullptr);
    combine_kernel<<<NTOK, 256>>>(b2, (float4*)d_out);
}